// round 7
// baseline (speedup 1.0000x reference)
#include <cuda_runtime.h>
#include <math_constants.h>

#define BB 8
#define CC 256
#define HH 128
#define WW 128
#define HW (HH*WW)
#define TOPK 10
#define THRESH 0.5f
#define MARGIN 0.5f
#define EPSV 1e-8f
#define NMAPS 16
#define NSLICE 32            // stream slices per map, 4 rows each
#define NREG 8               // detection regions per map, 16 rows each
#define JPIX (16*WW)         // 2048 pixels per region
#define PADW 130
#define STG_ROWS 18          // 16 rows + halo
#define NT 256

// scratch (no allocations); all counters self-reset -> graph-replay-safe
__device__ float    g_intensity[NMAPS][HW];
__device__ float    g_part_val[NMAPS][NREG][TOPK];
__device__ int      g_part_idx[NMAPS][NREG][TOPK];
__device__ float    g_losses[BB];
__device__ unsigned g_reg_cnt[NMAPS][NREG];
__device__ unsigned g_samp_cnt[BB];
__device__ unsigned g_done_cnt;

__global__ void __launch_bounds__(NT) fused_kernel(
    const float* __restrict__ det, const float* __restrict__ loc,
    float* __restrict__ out)
{
    // 20KB phase-union buffer
    __shared__ float buf[5120];
    float* rawp   = buf;                    // region: STG_ROWS*PADW = 2340
    float* masked = buf + 2560;             // region: JPIX = 2048
    float (*df)[CC] = (float(*)[CC])buf;            // loss alias
    float (*lf)[CC] = (float(*)[CC])(buf + 2560);   // loss alias

    __shared__ float4 s_part[128];          // stream channel-half combine
    __shared__ float s_wval[8][TOPK];
    __shared__ int   s_widx[8][TOPK];
    __shared__ float s_mv[2][NREG * TOPK];
    __shared__ int   s_mi[2][NREG * TOPK];
    __shared__ float s_dkv[TOPK], s_lkv[TOPK], s_na[TOPK], s_nb[TOPK], s_ws[8];
    __shared__ int   s_dki[TOPK], s_lki[TOPK];
    __shared__ int   s_claims[2], s_nclaim, s_doloss;

    const int tid  = threadIdx.x;
    const int lane = tid & 31;
    const int w    = tid >> 5;              // 8 warps
    const int bid  = blockIdx.x;            // 0..511
    const int m    = bid >> 5;              // map 0..15 (0..7 det, 8..15 loc)
    const int sl   = bid & 31;              // stream slice (rows 4sl..4sl+3)
    const int b    = m & 7;

    // ============ Phase S: intensity stream slice (unchanged R4 pattern) ====
    {
        const int half = tid >> 7;
        const int gl   = tid & 127;
        const int g    = sl * 128 + gl;
        const float* src = (m < 8) ? det : loc;
        const float4* base = ((const float4*)(src + (size_t)b * CC * HW))
                             + g + (size_t)half * 128 * (HW / 4);
        float a0 = 0.f, a1 = 0.f, a2 = 0.f, a3 = 0.f;
        #pragma unroll 8
        for (int c = 0; c < 128; c++) {
            float4 v = __ldcs(base + (size_t)c * (HW / 4));
            a0 = fmaf(v.x, v.x, a0);
            a1 = fmaf(v.y, v.y, a1);
            a2 = fmaf(v.z, v.z, a2);
            a3 = fmaf(v.w, v.w, a3);
        }
        if (half) s_part[gl] = make_float4(a0, a1, a2, a3);
        __syncthreads();
        if (!half) {
            float4 p = s_part[gl];
            float4 o;
            o.x = sqrtf(a0 + p.x);
            o.y = sqrtf(a1 + p.y);
            o.z = sqrtf(a2 + p.z);
            o.w = sqrtf(a3 + p.w);
            ((float4*)g_intensity[m])[g] = o;
        }
    }
    __syncthreads();

    // ============ Claim regions whose dependencies this slice completes =====
    if (tid == 0) {
        __threadfence();
        int nc = 0;
        s_doloss = 0;
        #pragma unroll
        for (int j = 0; j < NREG; j++) {
            int lo = max(0, 16 * j - 1);
            int hi = min(HH - 1, 16 * j + 16);
            bool dep = (lo <= 4 * sl + 3) && (hi >= 4 * sl);
            if (dep) {
                unsigned target = (unsigned)(hi / 4 - lo / 4 + 1);  // 5 or 6
                unsigned old = atomicAdd(&g_reg_cnt[m][j], 1u);
                if (old == target - 1u) {
                    g_reg_cnt[m][j] = 0u;        // reset for replay
                    s_claims[nc++] = j;
                }
            }
        }
        s_nclaim = nc;
    }
    __syncthreads();
    if (s_nclaim == 0) return;

    // ============ Phase R: detection + top-10 for each claimed region =======
    __threadfence();   // acquire intensity rows published by other CTAs
    for (int r = 0; r < s_nclaim; r++) {
        const int j = s_claims[r];

        // stage 16 rows + halo, padded, -inf border (L2-hot: written moments ago)
        for (int i = tid; i < STG_ROWS * PADW; i += NT) rawp[i] = -CUDART_INF_F;
        __syncthreads();
        {
            const float* gi = g_intensity[m];
            for (int i = tid; i < STG_ROWS * WW; i += NT) {
                int rr = i >> 7, x = i & 127;
                int grow = j * 16 - 1 + rr;
                if (grow >= 0 && grow < HH)
                    rawp[rr * PADW + x + 1] = __ldcg(&gi[(grow << 7) + x]);
            }
        }
        __syncthreads();

        // branch-free 3x3 strict maxima
        for (int p = tid; p < JPIX; p += NT) {
            int yl = p >> 7, x = p & 127;
            const float* c = &rawp[(yl + 1) * PADW + (x + 1)];
            float v = c[0];
            float n0 = fmaxf(fmaxf(c[-PADW - 1], c[-PADW]), c[-PADW + 1]);
            float n1 = fmaxf(c[-1], c[1]);
            float n2 = fmaxf(fmaxf(c[PADW - 1], c[PADW]), c[PADW + 1]);
            float nmax = fmaxf(fmaxf(n0, n1), n2);
            masked[p] = (v > THRESH && v >= nmax) ? v : -CUDART_INF_F;
        }
        __syncthreads();

        // per-warp top-10 over 256-pixel slice
        {
            const int base2 = w * 256;
            for (int k = 0; k < TOPK; k++) {
                float bv = -CUDART_INF_F; int bp = 0x7fffffff;
                #pragma unroll
                for (int q = 0; q < 8; q++) {
                    int p = base2 + q * 32 + lane;
                    float v = masked[p];
                    if (v > bv || (v == bv && p < bp)) { bv = v; bp = p; }
                }
                #pragma unroll
                for (int o = 16; o > 0; o >>= 1) {
                    float v2 = __shfl_down_sync(0xffffffffu, bv, o);
                    int   p2 = __shfl_down_sync(0xffffffffu, bp, o);
                    if (v2 > bv || (v2 == bv && p2 < bp)) { bv = v2; bp = p2; }
                }
                bv = __shfl_sync(0xffffffffu, bv, 0);
                bp = __shfl_sync(0xffffffffu, bp, 0);
                if (lane == 0) {
                    s_wval[w][k] = bv;
                    s_widx[w][k] = j * JPIX + bp;   // global pixel index
                    masked[bp] = -CUDART_INF_F;
                }
                __syncwarp();
            }
        }
        __syncthreads();

        // warp 0: merge 80 -> region top-10 -> g_part
        if (w == 0) {
            float* fv = &s_wval[0][0];
            int*   fi = &s_widx[0][0];
            for (int k = 0; k < TOPK; k++) {
                float bv = -CUDART_INF_F; int bi = 0x7fffffff; int bp = -1;
                #pragma unroll
                for (int q = 0; q < 3; q++) {
                    int p = q * 32 + lane;
                    if (p < 80) {
                        float v = fv[p]; int i = fi[p];
                        if (v > bv || (v == bv && i < bi)) { bv = v; bi = i; bp = p; }
                    }
                }
                #pragma unroll
                for (int o = 16; o > 0; o >>= 1) {
                    float v2 = __shfl_down_sync(0xffffffffu, bv, o);
                    int   i2 = __shfl_down_sync(0xffffffffu, bi, o);
                    int   p2 = __shfl_down_sync(0xffffffffu, bp, o);
                    if (v2 > bv || (v2 == bv && i2 < bi)) { bv = v2; bi = i2; bp = p2; }
                }
                bp = __shfl_sync(0xffffffffu, bp, 0);
                if (lane == 0) {
                    g_part_val[m][j][k] = bv;
                    g_part_idx[m][j][k] = bi;
                    if (bp >= 0) fv[bp] = -CUDART_INF_F;
                }
                __syncwarp();
            }
        }
        __syncthreads();

        // count region completion toward sample b (16 regions across 2 maps)
        if (tid == 0) {
            __threadfence();
            unsigned old = atomicAdd(&g_samp_cnt[b], 1u);
            if (old == 15u) { g_samp_cnt[b] = 0u; s_doloss = 1; }
        }
        __syncthreads();
    }
    if (!s_doloss) return;

    // ============ Phase L: cosine-sim loss for sample b ======================
    __threadfence();
    // merge 80 partials per map: warp0 = det(map b), warp1 = loc(map 8+b)
    if (w < 2) {
        const int mm = (w == 0) ? b : (8 + b);
        const float* pv = &g_part_val[mm][0][0];
        const int*   pi = &g_part_idx[mm][0][0];
        for (int p = lane; p < 80; p += 32) {
            s_mv[w][p] = __ldcg(&pv[p]);
            s_mi[w][p] = __ldcg(&pi[p]);
        }
        __syncwarp();
        for (int k = 0; k < TOPK; k++) {
            float bv = -CUDART_INF_F; int bi = 0x7fffffff; int bp = -1;
            #pragma unroll
            for (int q = 0; q < 3; q++) {
                int p = q * 32 + lane;
                if (p < 80) {
                    float v = s_mv[w][p]; int i = s_mi[w][p];
                    if (v > bv || (v == bv && i < bi)) { bv = v; bi = i; bp = p; }
                }
            }
            #pragma unroll
            for (int o = 16; o > 0; o >>= 1) {
                float v2 = __shfl_down_sync(0xffffffffu, bv, o);
                int   i2 = __shfl_down_sync(0xffffffffu, bi, o);
                int   p2 = __shfl_down_sync(0xffffffffu, bp, o);
                if (v2 > bv || (v2 == bv && i2 < bi)) { bv = v2; bi = i2; bp = p2; }
            }
            bp = __shfl_sync(0xffffffffu, bp, 0);
            if (lane == 0) {
                if (w == 0) { s_dkv[k] = bv; s_dki[k] = (bv > -CUDART_INF_F) ? bi : 0; }
                else        { s_lkv[k] = bv; s_lki[k] = (bv > -CUDART_INF_F) ? bi : 0; }
                if (bp >= 0) s_mv[w][bp] = -CUDART_INF_F;
            }
            __syncwarp();
        }
    }
    __syncthreads();   // region smem dead before alias overwrite

    // gather features [10][256] x2
    {
        const float* dbase = det + (size_t)b * CC * HW;
        const float* lbase = loc + (size_t)b * CC * HW;
        for (int idx = tid; idx < TOPK * CC; idx += NT) {
            int k = idx >> 8, c = idx & 255;
            df[k][c] = __ldg(&dbase[(size_t)c * HW + s_dki[k]]);
            lf[k][c] = __ldg(&lbase[(size_t)c * HW + s_lki[k]]);
        }
    }
    __syncthreads();

    // norms (warp-per-row)
    for (int k = w; k < TOPK; k += 8) {
        float sa = 0.f, sb = 0.f;
        #pragma unroll
        for (int c = lane; c < CC; c += 32) {
            sa = fmaf(df[k][c], df[k][c], sa);
            sb = fmaf(lf[k][c], lf[k][c], sb);
        }
        #pragma unroll
        for (int o = 16; o > 0; o >>= 1) {
            sa += __shfl_down_sync(0xffffffffu, sa, o);
            sb += __shfl_down_sync(0xffffffffu, sb, o);
        }
        if (lane == 0) {
            s_na[k] = fmaxf(sqrtf(sa), EPSV);
            s_nb[k] = fmaxf(sqrtf(sb), EPSV);
        }
    }
    __syncthreads();

    // 100 pair dots over 8 warps
    float lsum = 0.f;
    for (int p = w; p < TOPK * TOPK; p += 8) {
        int i = p / TOPK, jj = p % TOPK;
        float dot = 0.f;
        #pragma unroll
        for (int c = lane; c < CC; c += 32) dot = fmaf(df[i][c], lf[jj][c], dot);
        #pragma unroll
        for (int o = 16; o > 0; o >>= 1)
            dot += __shfl_down_sync(0xffffffffu, dot, o);
        if (lane == 0 && s_dkv[i] > -CUDART_INF_F && s_lkv[jj] > -CUDART_INF_F)
            lsum += fmaxf(dot / (s_na[i] * s_nb[jj]) - MARGIN, 0.f);
    }
    if (lane == 0) s_ws[w] = lsum;
    __syncthreads();

    if (tid == 0) {
        int nd = 0, nl = 0;
        #pragma unroll
        for (int k = 0; k < TOPK; k++) {
            nd += (s_dkv[k] > -CUDART_INF_F) ? 1 : 0;
            nl += (s_lkv[k] > -CUDART_INF_F) ? 1 : 0;
        }
        float ssum = 0.f;
        #pragma unroll
        for (int q = 0; q < 8; q++) ssum += s_ws[q];
        int np = nd * nl;
        g_losses[b] = (np > 0) ? (ssum / (float)np) : 0.f;

        // last loss CTA writes the scalar (fixed-order sum, deterministic)
        __threadfence();
        unsigned old = atomicAdd(&g_done_cnt, 1u);
        if (old == (BB - 1)) {
            g_done_cnt = 0u;   // reset for replay
            __threadfence();
            float tot = 0.f;
            #pragma unroll
            for (int q = 0; q < BB; q++) tot += __ldcg(&g_losses[q]);
            out[0] = tot / (float)BB;
        }
    }
}

extern "C" void kernel_launch(void* const* d_in, const int* in_sizes, int n_in,
                              void* d_out, int out_size)
{
    const float* loc = (const float*)d_in[0];   // loc_features [8,256,128,128]
    const float* det = (const float*)d_in[1];   // det_features [8,256,128,128]
    float* out = (float*)d_out;

    fused_kernel<<<NMAPS * NSLICE, NT>>>(det, loc, out);
}

// round 8
// speedup vs baseline: 1.1372x; 1.1372x over previous
#include <cuda_runtime.h>
#include <math_constants.h>

#define BB 8
#define CC 256
#define HH 128
#define WW 128
#define HW (HH*WW)
#define TOPK 10
#define THRESH 0.5f
#define MARGIN 0.5f
#define EPSV 1e-8f
#define NMAPS 16
#define JCTAS 8                    // tail CTAs per map
#define JROWS 16                   // rows per tail CTA
#define JPIX (JROWS*WW)            // 2048 pixels per tail CTA
#define PADW 130
#define STG_ROWS 18                // 16 rows + halo
#define T2 256

// scratch (no allocations allowed); counters self-reset -> replay-safe
__device__ float    g_intensity[NMAPS][HW];
__device__ float    g_part_val[NMAPS][JCTAS][TOPK];
__device__ int      g_part_idx[NMAPS][JCTAS][TOPK];
__device__ float    g_losses[BB];
__device__ unsigned g_samp_cnt[BB];
__device__ unsigned g_done_cnt;

// ---------------------------------------------------------------------------
// Kernel 1: intensity stream, v2. 512 CTAs x 256 thr.
// KEY CHANGE vs R6: explicit 8-deep load batching (v[8] loaded in a dedicated
// unrolled loop BEFORE any FMA consumes it) -> guaranteed >=8 LDG.128 in
// flight per thread. R2 vs R7 showed warp count (8 -> 27/SM) doesn't move
// BW (~3.3TB/s), so per-thread MLP is the binding constraint.
// ---------------------------------------------------------------------------
__global__ void __launch_bounds__(256) intensity_kernel(
    const float* __restrict__ det, const float* __restrict__ loc)
{
    __shared__ float4 s_part[128];

    const int bid  = blockIdx.x;
    const int m    = bid >> 5;
    const int sl   = bid & 31;
    const int b    = m & 7;
    const int tid  = threadIdx.x;
    const int half = tid >> 7;
    const int gl   = tid & 127;
    const int g    = sl * 128 + gl;

    const float* src = (m < 8) ? det : loc;
    const float4* base = ((const float4*)(src + (size_t)b * CC * HW))
                         + g + (size_t)half * 128 * (HW / 4);

    float a0 = 0.f, a1 = 0.f, a2 = 0.f, a3 = 0.f;
    #pragma unroll 1
    for (int c0 = 0; c0 < 128; c0 += 8) {
        float4 v[8];
        #pragma unroll
        for (int i = 0; i < 8; i++)
            v[i] = __ldcs(base + (size_t)(c0 + i) * (HW / 4));
        #pragma unroll
        for (int i = 0; i < 8; i++) {
            a0 = fmaf(v[i].x, v[i].x, a0);
            a1 = fmaf(v[i].y, v[i].y, a1);
            a2 = fmaf(v[i].z, v[i].z, a2);
            a3 = fmaf(v[i].w, v[i].w, a3);
        }
    }
    if (half) s_part[gl] = make_float4(a0, a1, a2, a3);
    __syncthreads();
    if (!half) {
        float4 p = s_part[gl];
        float4 o;
        o.x = sqrtf(a0 + p.x);
        o.y = sqrtf(a1 + p.y);
        o.z = sqrtf(a2 + p.z);
        o.w = sqrtf(a3 + p.w);
        ((float4*)g_intensity[m])[g] = o;
    }
}

// ---------------------------------------------------------------------------
// Kernel 2: tail (UNCHANGED from R6 — wall-clock ~9us; the 40us ncu reading
// was a cache-flush artifact). 128 CTAs x 256 thr.
// ---------------------------------------------------------------------------
__global__ void __launch_bounds__(T2) tail_kernel(
    const float* __restrict__ det, const float* __restrict__ loc,
    float* __restrict__ out)
{
    __shared__ float sbuf[5120];                  // 20KB, phase-aliased
    float* rawp   = sbuf;                         // STG_ROWS*PADW = 2340
    float* masked = sbuf + 2560;                  // JPIX = 2048
    float (*df)[CC] = (float(*)[CC])sbuf;         // loss alias: 2560
    float (*lf)[CC] = (float(*)[CC])(sbuf + 2560);// loss alias: 2560

    __shared__ float s_wval[8][TOPK];
    __shared__ int   s_widx[8][TOPK];
    __shared__ float s_mv[2][JCTAS * TOPK];
    __shared__ int   s_mi[2][JCTAS * TOPK];
    __shared__ float s_dkv[TOPK], s_lkv[TOPK];
    __shared__ int   s_dki[TOPK], s_lki[TOPK];
    __shared__ float s_na[TOPK], s_nb[TOPK], s_ws[8];
    __shared__ unsigned s_flag;

    const int tid  = threadIdx.x;
    const int lane = tid & 31;
    const int w    = tid >> 5;                    // 8 warps
    const int m    = blockIdx.x >> 3;             // map 0..15
    const int j    = blockIdx.x & 7;              // region within map
    const int b    = m & 7;

    // ---- stage 16 rows + halo into padded smem (-inf border) ---------------
    for (int i = tid; i < STG_ROWS * PADW; i += T2) rawp[i] = -CUDART_INF_F;
    __syncthreads();
    {
        const float* gi = g_intensity[m];
        for (int i = tid; i < STG_ROWS * WW; i += T2) {
            int r = i >> 7, x = i & 127;
            int grow = j * JROWS - 1 + r;
            if (grow >= 0 && grow < HH)
                rawp[r * PADW + x + 1] = __ldcg(&gi[(grow << 7) + x]);
        }
    }
    __syncthreads();

    // ---- branch-free 3x3 strict maxima over 2048 local pixels --------------
    for (int p = tid; p < JPIX; p += T2) {
        int yl = p >> 7, x = p & 127;
        const float* c = &rawp[(yl + 1) * PADW + (x + 1)];
        float v = c[0];
        float n0 = fmaxf(fmaxf(c[-PADW - 1], c[-PADW]), c[-PADW + 1]);
        float n1 = fmaxf(c[-1], c[1]);
        float n2 = fmaxf(fmaxf(c[PADW - 1], c[PADW]), c[PADW + 1]);
        float nmax = fmaxf(fmaxf(n0, n1), n2);
        masked[p] = (v > THRESH && v >= nmax) ? v : -CUDART_INF_F;
    }
    __syncthreads();

    // ---- per-warp top-10 over its 256-pixel slice ---------------------------
    {
        const int base = w * 256;
        for (int k = 0; k < TOPK; k++) {
            float bv = -CUDART_INF_F; int bp = 0x7fffffff;
            #pragma unroll
            for (int q = 0; q < 8; q++) {
                int p = base + q * 32 + lane;
                float v = masked[p];
                if (v > bv || (v == bv && p < bp)) { bv = v; bp = p; }
            }
            #pragma unroll
            for (int o = 16; o > 0; o >>= 1) {
                float v2 = __shfl_down_sync(0xffffffffu, bv, o);
                int   p2 = __shfl_down_sync(0xffffffffu, bp, o);
                if (v2 > bv || (v2 == bv && p2 < bp)) { bv = v2; bp = p2; }
            }
            bv = __shfl_sync(0xffffffffu, bv, 0);
            bp = __shfl_sync(0xffffffffu, bp, 0);
            if (lane == 0) {
                s_wval[w][k] = bv;
                s_widx[w][k] = j * JPIX + bp;      // global pixel index
                masked[bp] = -CUDART_INF_F;
            }
            __syncwarp();
        }
    }
    __syncthreads();

    // ---- warp 0 merges 80 -> region top-10 -> g_part ------------------------
    if (w == 0) {
        float* fv = &s_wval[0][0];
        int*   fi = &s_widx[0][0];
        for (int k = 0; k < TOPK; k++) {
            float bv = -CUDART_INF_F; int bi = 0x7fffffff; int bp = -1;
            #pragma unroll
            for (int q = 0; q < 3; q++) {
                int p = q * 32 + lane;
                if (p < 80) {
                    float v = fv[p]; int i = fi[p];
                    if (v > bv || (v == bv && i < bi)) { bv = v; bi = i; bp = p; }
                }
            }
            #pragma unroll
            for (int o = 16; o > 0; o >>= 1) {
                float v2 = __shfl_down_sync(0xffffffffu, bv, o);
                int   i2 = __shfl_down_sync(0xffffffffu, bi, o);
                int   p2 = __shfl_down_sync(0xffffffffu, bp, o);
                if (v2 > bv || (v2 == bv && i2 < bi)) { bv = v2; bi = i2; bp = p2; }
            }
            bp = __shfl_sync(0xffffffffu, bp, 0);
            if (lane == 0) {
                g_part_val[m][j][k] = bv;
                g_part_idx[m][j][k] = bi;
                if (bp >= 0) fv[bp] = -CUDART_INF_F;
            }
            __syncwarp();
        }
    }
    __syncthreads();
    if (tid == 0) {
        __threadfence();
        unsigned old = atomicAdd(&g_samp_cnt[b], 1u);
        if (old == 15u) g_samp_cnt[b] = 0u;        // reset for replay
        s_flag = (old == 15u);
    }
    __syncthreads();
    if (!s_flag) return;   // last of the sample's 16 CTAs computes the loss

    // ---- merge 80 partials per map: warp0 = det(map b), warp1 = loc(8+b) ---
    __threadfence();
    if (w < 2) {
        const int mm = (w == 0) ? b : (8 + b);
        const float* pv = &g_part_val[mm][0][0];
        const int*   pi = &g_part_idx[mm][0][0];
        for (int p = lane; p < 80; p += 32) {
            s_mv[w][p] = __ldcg(&pv[p]);
            s_mi[w][p] = __ldcg(&pi[p]);
        }
        __syncwarp();
        for (int k = 0; k < TOPK; k++) {
            float bv = -CUDART_INF_F; int bi = 0x7fffffff; int bp = -1;
            #pragma unroll
            for (int q = 0; q < 3; q++) {
                int p = q * 32 + lane;
                if (p < 80) {
                    float v = s_mv[w][p]; int i = s_mi[w][p];
                    if (v > bv || (v == bv && i < bi)) { bv = v; bi = i; bp = p; }
                }
            }
            #pragma unroll
            for (int o = 16; o > 0; o >>= 1) {
                float v2 = __shfl_down_sync(0xffffffffu, bv, o);
                int   i2 = __shfl_down_sync(0xffffffffu, bi, o);
                int   p2 = __shfl_down_sync(0xffffffffu, bp, o);
                if (v2 > bv || (v2 == bv && i2 < bi)) { bv = v2; bi = i2; bp = p2; }
            }
            bp = __shfl_sync(0xffffffffu, bp, 0);
            if (lane == 0) {
                if (w == 0) { s_dkv[k] = bv; s_dki[k] = (bv > -CUDART_INF_F) ? bi : 0; }
                else        { s_lkv[k] = bv; s_lki[k] = (bv > -CUDART_INF_F) ? bi : 0; }
                if (bp >= 0) s_mv[w][bp] = -CUDART_INF_F;
            }
            __syncwarp();
        }
    }
    __syncthreads();   // detection smem dead before alias overwrite

    // ---- gather features [10][256] x2 (20 scattered loads/thread) ----------
    {
        const float* dbase = det + (size_t)b * CC * HW;
        const float* lbase = loc + (size_t)b * CC * HW;
        for (int idx = tid; idx < TOPK * CC; idx += T2) {
            int k = idx >> 8, c = idx & 255;
            df[k][c] = __ldg(&dbase[(size_t)c * HW + s_dki[k]]);
            lf[k][c] = __ldg(&lbase[(size_t)c * HW + s_lki[k]]);
        }
    }
    __syncthreads();

    // ---- norms (warp-per-row) ----------------------------------------------
    for (int k = w; k < TOPK; k += 8) {
        float sa = 0.f, sb = 0.f;
        #pragma unroll
        for (int c = lane; c < CC; c += 32) {
            sa = fmaf(df[k][c], df[k][c], sa);
            sb = fmaf(lf[k][c], lf[k][c], sb);
        }
        #pragma unroll
        for (int o = 16; o > 0; o >>= 1) {
            sa += __shfl_down_sync(0xffffffffu, sa, o);
            sb += __shfl_down_sync(0xffffffffu, sb, o);
        }
        if (lane == 0) {
            s_na[k] = fmaxf(sqrtf(sa), EPSV);
            s_nb[k] = fmaxf(sqrtf(sb), EPSV);
        }
    }
    __syncthreads();

    // ---- 100 pair dots over 8 warps ----------------------------------------
    float lsum = 0.f;
    for (int p = w; p < TOPK * TOPK; p += 8) {
        int i = p / TOPK, jj = p % TOPK;
        float dot = 0.f;
        #pragma unroll
        for (int c = lane; c < CC; c += 32) dot = fmaf(df[i][c], lf[jj][c], dot);
        #pragma unroll
        for (int o = 16; o > 0; o >>= 1)
            dot += __shfl_down_sync(0xffffffffu, dot, o);
        if (lane == 0 && s_dkv[i] > -CUDART_INF_F && s_lkv[jj] > -CUDART_INF_F)
            lsum += fmaxf(dot / (s_na[i] * s_nb[jj]) - MARGIN, 0.f);
    }
    if (lane == 0) s_ws[w] = lsum;
    __syncthreads();

    if (tid == 0) {
        int nd = 0, nl = 0;
        #pragma unroll
        for (int k = 0; k < TOPK; k++) {
            nd += (s_dkv[k] > -CUDART_INF_F) ? 1 : 0;
            nl += (s_lkv[k] > -CUDART_INF_F) ? 1 : 0;
        }
        float ssum = 0.f;
        #pragma unroll
        for (int q = 0; q < 8; q++) ssum += s_ws[q];
        int np = nd * nl;
        g_losses[b] = (np > 0) ? (ssum / (float)np) : 0.f;

        // last loss CTA writes the scalar (fixed-order, deterministic)
        __threadfence();
        unsigned old = atomicAdd(&g_done_cnt, 1u);
        if (old == (BB - 1)) {
            g_done_cnt = 0u;   // reset for replay
            __threadfence();
            float tot = 0.f;
            #pragma unroll
            for (int q = 0; q < BB; q++) tot += __ldcg(&g_losses[q]);
            out[0] = tot / (float)BB;
        }
    }
}

extern "C" void kernel_launch(void* const* d_in, const int* in_sizes, int n_in,
                              void* d_out, int out_size)
{
    const float* loc = (const float*)d_in[0];   // loc_features [8,256,128,128]
    const float* det = (const float*)d_in[1];   // det_features [8,256,128,128]
    float* out = (float*)d_out;

    intensity_kernel<<<512, 256>>>(det, loc);
    tail_kernel<<<NMAPS * JCTAS, T2>>>(det, loc, out);
}